// round 1
// baseline (speedup 1.0000x reference)
#include <cuda_runtime.h>
#include <cuda_bf16.h>

// ---------------------------------------------------------------------------
// RBF layer: out[b,o] = exp(-max(||x_b||^2 - 2 x_b.c_o + ||c_o||^2, 0) * exp(-2*ls_o))
// B=8192, IN=512, OUT=1024 (shapes derived from in_sizes; tiles assume
// B%128==0, OUT%128==0, IN%32==0, IN%16==0 which hold here).
// ---------------------------------------------------------------------------

#define MAX_B   8192
#define MAX_OUT 1024

__device__ float g_xsq[MAX_B];
__device__ float g_csq[MAX_OUT];
__device__ float g_inv[MAX_OUT];   // exp(-2*log_sigma)

// ---- row squared-norm: one warp per row, IN floats per row (IN%16==0, >=... IN=512) ----
__global__ void rownorm_kernel(const float* __restrict__ x, float* __restrict__ out,
                               int nrows, int IN) {
    int warp = (blockIdx.x * blockDim.x + threadIdx.x) >> 5;
    int lane = threadIdx.x & 31;
    if (warp >= nrows) return;
    const float4* p = (const float4*)(x + (size_t)warp * IN);
    int nf4 = IN >> 2;                // 128 for IN=512
    float s = 0.f;
    for (int i = lane; i < nf4; i += 32) {
        float4 v = p[i];
        s += v.x * v.x + v.y * v.y + v.z * v.z + v.w * v.w;
    }
    #pragma unroll
    for (int o = 16; o; o >>= 1) s += __shfl_xor_sync(0xffffffffu, s, o);
    if (lane == 0) out[warp] = s;
}

__global__ void sigma_kernel(const float* __restrict__ ls, int OUTN) {
    int i = blockIdx.x * blockDim.x + threadIdx.x;
    if (i < OUTN) g_inv[i] = __expf(-2.0f * ls[i]);
}

// ---- fused GEMM + RBF epilogue ----
// C-equivalent: dot[b,o] = sum_k A[b,k]*Cc[o,k]  (NT gemm, both K-contiguous)
#define BM 128
#define BN 128
#define BK 32
#define TM 8
#define TN 8

__global__ __launch_bounds__(256, 2)
void rbf_gemm_kernel(const float* __restrict__ A,   // [B, IN]
                     const float* __restrict__ Cc,  // [OUT, IN]
                     float* __restrict__ out,       // [B, OUT]
                     int IN, int OUTN) {
    __shared__ float As[BK][BM + 4];
    __shared__ float Bs[BK][BN + 4];

    const int tid  = threadIdx.x;
    const int brow = blockIdx.y * BM;   // batch dim
    const int bcol = blockIdx.x * BN;   // out dim

    const int tr = tid >> 4;            // 0..15
    const int tc = tid & 15;            // 0..15

    // loader mapping: 256 threads, each loads 4x float4 per tile per operand
    const int lrow = tid >> 3;          // 0..31
    const int lcol = (tid & 7) << 2;    // float col within BK, multiple of 4

    float acc[TM][TN];
    #pragma unroll
    for (int i = 0; i < TM; i++)
        #pragma unroll
        for (int j = 0; j < TN; j++) acc[i][j] = 0.f;

    for (int k0 = 0; k0 < IN; k0 += BK) {
        #pragma unroll
        for (int i = 0; i < 4; i++) {
            int r = lrow + 32 * i;
            float4 va = *(const float4*)(A  + (size_t)(brow + r) * IN + k0 + lcol);
            As[lcol + 0][r] = va.x;
            As[lcol + 1][r] = va.y;
            As[lcol + 2][r] = va.z;
            As[lcol + 3][r] = va.w;
            float4 vb = *(const float4*)(Cc + (size_t)(bcol + r) * IN + k0 + lcol);
            Bs[lcol + 0][r] = vb.x;
            Bs[lcol + 1][r] = vb.y;
            Bs[lcol + 2][r] = vb.z;
            Bs[lcol + 3][r] = vb.w;
        }
        __syncthreads();

        #pragma unroll
        for (int k = 0; k < BK; k++) {
            float a[TM], b[TN];
            #pragma unroll
            for (int i = 0; i < TM; i++) a[i] = As[k][tr * TM + i];
            #pragma unroll
            for (int j = 0; j < TN; j++) b[j] = Bs[k][tc * TN + j];
            #pragma unroll
            for (int i = 0; i < TM; i++)
                #pragma unroll
                for (int j = 0; j < TN; j++)
                    acc[i][j] = fmaf(a[i], b[j], acc[i][j]);
        }
        __syncthreads();
    }

    // epilogue: d2 = max(xsq - 2*dot + csq, 0); out = exp(-d2 * inv)
    #pragma unroll
    for (int i = 0; i < TM; i++) {
        int r = brow + tr * TM + i;
        float xs = g_xsq[r];
        #pragma unroll
        for (int j = 0; j < TN; j++) {
            int c = bcol + tc * TN + j;
            float d2 = fmaxf(fmaf(-2.0f, acc[i][j], xs + g_csq[c]), 0.0f);
            out[(size_t)r * OUTN + c] = __expf(-d2 * g_inv[c]);
        }
    }
}

extern "C" void kernel_launch(void* const* d_in, const int* in_sizes, int n_in,
                              void* d_out, int out_size) {
    const float* input   = (const float*)d_in[0];   // [B, IN]
    const float* centres = (const float*)d_in[1];   // [OUT, IN]
    const float* lsig    = (const float*)d_in[2];   // [OUT]
    float* out = (float*)d_out;

    const int OUTN = in_sizes[2];
    const int IN   = in_sizes[1] / OUTN;
    const int B    = in_sizes[0] / IN;

    // resolve device-symbol addresses (no allocation, not a stream op)
    float *xsq_p = nullptr, *csq_p = nullptr;
    cudaGetSymbolAddress((void**)&xsq_p, g_xsq);
    cudaGetSymbolAddress((void**)&csq_p, g_csq);

    // 1) squared norms (warp per row)
    {
        int warps = B;
        int blocks = (warps * 32 + 255) / 256;
        rownorm_kernel<<<blocks, 256>>>(input, xsq_p, B, IN);
    }
    {
        int warps = OUTN;
        int blocks = (warps * 32 + 255) / 256;
        rownorm_kernel<<<blocks, 256>>>(centres, csq_p, OUTN, IN);
    }
    // 2) sigma factors
    sigma_kernel<<<(OUTN + 255) / 256, 256>>>(lsig, OUTN);

    // 3) fused GEMM + RBF epilogue
    dim3 grid(OUTN / BN, B / BM);
    rbf_gemm_kernel<<<grid, 256>>>(input, centres, out, IN, OUTN);
}

// round 3
// speedup vs baseline: 6.0202x; 6.0202x over previous
#include <cuda_runtime.h>
#include <cuda_bf16.h>
#include <cstdint>

// ===========================================================================
// RBF layer (sm_103, legacy tensor path: mma.sync bf16 + cp.async + ldmatrix)
//   out[b,o] = exp(-max(||x_b||^2 - 2 x_b.c_o + ||c_o||^2, 0) * exp(-2*ls_o))
// B=8192, IN=512, OUT=1024. GEMM in bf16 (numerically safe: d2 ~ 1024±64,
// outputs underflow exp() by ~600 in the exponent).
// NOTE: tcgen05/TMEM PTX rejected by this harness's ptxas target (sm_103,
// not sm_103a) -- verified round 2. mma.sync / cp.async / ldmatrix assemble.
// ===========================================================================

#define MAX_B   8192
#define MAX_OUT 1024
#define MAX_IN  512

__device__ __nv_bfloat16 g_Abf[MAX_B * MAX_IN];
__device__ __nv_bfloat16 g_Cbf[MAX_OUT * MAX_IN];
__device__ float g_xsq[MAX_B];
__device__ float g_csq[MAX_OUT];
__device__ float g_inv[MAX_OUT];

// ---------------------------------------------------------------------------
__device__ __forceinline__ uint32_t smem_to_u32(const void* smem_ptr) {
    uint32_t addr;
    asm("{ .reg .u64 tmp; cvta.to.shared.u64 tmp, %1; cvt.u32.u64 %0, tmp; }"
        : "=r"(addr) : "l"(smem_ptr));
    return addr;
}

#define SMEM_SWIZZLE_128B(byte_offset) \
    ((byte_offset) ^ (((byte_offset) >> 3) & 0x70))

#define CP_ASYNC16(dst_u32, src_ptr) \
    asm volatile("cp.async.cg.shared.global [%0], [%1], 16;" \
                 :: "r"(dst_u32), "l"(src_ptr) : "memory")
#define CP_COMMIT() asm volatile("cp.async.commit_group;" ::: "memory")
#define CP_WAIT1()  asm volatile("cp.async.wait_group 1;" ::: "memory")

#define LDSM4(r0, r1, r2, r3, addr) \
    asm volatile("ldmatrix.sync.aligned.m8n8.x4.shared.b16 {%0,%1,%2,%3}, [%4];" \
                 : "=r"(r0), "=r"(r1), "=r"(r2), "=r"(r3) : "r"(addr))

#define MMA16816(d, a, b) \
    asm volatile("mma.sync.aligned.m16n8k16.row.col.f32.bf16.bf16.f32 " \
                 "{%0,%1,%2,%3}, {%4,%5,%6,%7}, {%8,%9}, {%0,%1,%2,%3};" \
                 : "+f"((d)[0]), "+f"((d)[1]), "+f"((d)[2]), "+f"((d)[3]) \
                 : "r"((a)[0]), "r"((a)[1]), "r"((a)[2]), "r"((a)[3]), \
                   "r"((b)[0]), "r"((b)[1]))

// ---------------------------------------------------------------------------
// Pre-pass: fp32 -> bf16 convert + squared row norm (warp per row)
// ---------------------------------------------------------------------------
__global__ void convert_norm_kernel(const float* __restrict__ src,
                                    __nv_bfloat16* __restrict__ dst,
                                    float* __restrict__ nrm,
                                    int nrows, int IN) {
    int warp = (blockIdx.x * blockDim.x + threadIdx.x) >> 5;
    int lane = threadIdx.x & 31;
    if (warp >= nrows) return;
    const float4* p = (const float4*)(src + (size_t)warp * IN);
    uint4* q = (uint4*)(dst + (size_t)warp * IN);
    int n8 = IN >> 3;
    float s = 0.f;
    for (int i = lane; i < n8; i += 32) {
        float4 a = p[2 * i], b = p[2 * i + 1];
        s += a.x * a.x + a.y * a.y + a.z * a.z + a.w * a.w;
        s += b.x * b.x + b.y * b.y + b.z * b.z + b.w * b.w;
        union { __nv_bfloat162 h; uint32_t u; } c0, c1, c2, c3;
        c0.h = __floats2bfloat162_rn(a.x, a.y);
        c1.h = __floats2bfloat162_rn(a.z, a.w);
        c2.h = __floats2bfloat162_rn(b.x, b.y);
        c3.h = __floats2bfloat162_rn(b.z, b.w);
        uint4 v; v.x = c0.u; v.y = c1.u; v.z = c2.u; v.w = c3.u;
        q[i] = v;
    }
    #pragma unroll
    for (int o = 16; o; o >>= 1) s += __shfl_xor_sync(0xffffffffu, s, o);
    if (lane == 0) nrm[warp] = s;
}

__global__ void sigma_kernel(const float* __restrict__ ls, float* __restrict__ inv, int OUTN) {
    int i = blockIdx.x * blockDim.x + threadIdx.x;
    if (i < OUTN) inv[i] = __expf(-2.0f * ls[i]);
}

// ---------------------------------------------------------------------------
// GEMM + RBF epilogue.  CTA tile 128x128, BK=64 bf16 (128B rows, swizzled),
// 8 warps (2 M x 4 N), warp tile 64x32, double-buffered cp.async pipeline.
// ---------------------------------------------------------------------------
static constexpr int TILE_B  = 128 * 128;       // bytes per operand tile/stage
static constexpr int STAGE_B = 2 * TILE_B;      // A + B per stage
static constexpr int SMEM_TOTAL = 2 * STAGE_B;  // 65536

__global__ __launch_bounds__(256, 2)
void rbf_mma_kernel(const __nv_bfloat16* __restrict__ gA,
                    const __nv_bfloat16* __restrict__ gC,
                    float* __restrict__ out,
                    const float* __restrict__ xsq,
                    const float* __restrict__ csq,
                    const float* __restrict__ inv,
                    int IN, int OUTN, int kchunks) {
    extern __shared__ char smem[];
    const uint32_t smem_u32 = smem_to_u32(smem);
    const int tid = threadIdx.x;
    const int lid = tid & 31;
    const int wid = tid >> 5;
    const int warp_m = wid >> 2;                 // 0..1 -> 64 rows
    const int warp_n = wid & 3;                  // 0..3 -> 32 cols
    const int brow = blockIdx.y * 128;
    const int bcol = blockIdx.x * 128;

    float acc[4][4][4];
    #pragma unroll
    for (int mi = 0; mi < 4; mi++)
        #pragma unroll
        for (int ni = 0; ni < 4; ni++)
            #pragma unroll
            for (int e = 0; e < 4; e++) acc[mi][ni][e] = 0.f;

    // loader lane mapping: 1024 16B-chunks per tile, 256 threads x 4 iters
    const int l_row = tid >> 3;                  // base row (0..31), +32*t
    const int l_q   = tid & 7;                   // 16B chunk within 128B row
    const size_t rowpitch = (size_t)IN * 2;

    // ldmatrix lane mapping
    const int a_row_l  = warp_m * 64 + (lid & 15);            // + mi*16
    const int a_half   = (lid >> 4) & 1;
    const int b_row_l  = warp_n * 32 + ((lid >> 4) << 3) + (lid & 7);  // + nj*16
    const int b_half   = (lid >> 3) & 1;

#define LOAD_STAGE(s, k0) do { \
    const char* srcA_ = (const char*)gA + 2 * ((size_t)brow * IN + (k0)); \
    const char* srcB_ = (const char*)gC + 2 * ((size_t)bcol * IN + (k0)); \
    uint32_t dstA_ = smem_u32 + (s) * STAGE_B; \
    uint32_t dstB_ = dstA_ + TILE_B; \
    _Pragma("unroll") \
    for (int t = 0; t < 4; t++) { \
        int row_ = l_row + 32 * t; \
        uint32_t sw_ = SMEM_SWIZZLE_128B((uint32_t)(row_ * 128 + l_q * 16)); \
        CP_ASYNC16(dstA_ + sw_, srcA_ + (size_t)row_ * rowpitch + l_q * 16); \
        CP_ASYNC16(dstB_ + sw_, srcB_ + (size_t)row_ * rowpitch + l_q * 16); \
    } \
} while (0)

    LOAD_STAGE(0, 0);
    CP_COMMIT();
    if (kchunks > 1) LOAD_STAGE(1, 64);
    CP_COMMIT();

    for (int i = 0; i < kchunks; i++) {
        const int s = i & 1;
        CP_WAIT1();
        __syncthreads();

        const uint32_t aBase = smem_u32 + s * STAGE_B;
        const uint32_t bBase = aBase + TILE_B;
        #pragma unroll
        for (int kk = 0; kk < 4; kk++) {
            uint32_t a[4][4], b[4][2];
            #pragma unroll
            for (int mi = 0; mi < 4; mi++) {
                int row = a_row_l + mi * 16;
                uint32_t addr = aBase + row * 128 +
                    (((uint32_t)(kk * 32 + a_half * 16)) ^ ((row & 7) << 4));
                LDSM4(a[mi][0], a[mi][1], a[mi][2], a[mi][3], addr);
            }
            #pragma unroll
            for (int nj = 0; nj < 2; nj++) {
                int row = b_row_l + nj * 16;
                uint32_t addr = bBase + row * 128 +
                    (((uint32_t)(kk * 32 + b_half * 16)) ^ ((row & 7) << 4));
                LDSM4(b[nj * 2][0], b[nj * 2][1], b[nj * 2 + 1][0], b[nj * 2 + 1][1], addr);
            }
            #pragma unroll
            for (int mi = 0; mi < 4; mi++)
                #pragma unroll
                for (int ni = 0; ni < 4; ni++)
                    MMA16816(acc[mi][ni], a[mi], b[ni]);
        }

        __syncthreads();
        if (i + 2 < kchunks) LOAD_STAGE(s, (i + 2) * 64);
        CP_COMMIT();
    }

    // ---- fused RBF epilogue straight from accumulators --------------------
    // d-frag: regs 0,1 -> (row = lid/4, col = (lid%4)*2, +1); regs 2,3 -> row+8
    const int er = lid >> 2;
    const int ec = (lid & 3) * 2;
    #pragma unroll
    for (int mi = 0; mi < 4; mi++) {
        const int r0 = brow + warp_m * 64 + mi * 16 + er;
        const int r1 = r0 + 8;
        const float xs0 = xsq[r0];
        const float xs1 = xsq[r1];
        #pragma unroll
        for (int ni = 0; ni < 4; ni++) {
            const int c = bcol + warp_n * 32 + ni * 8 + ec;
            const float cs0 = csq[c],  cs1 = csq[c + 1];
            const float iv0 = inv[c],  iv1 = inv[c + 1];
            float2 v0, v1;
            v0.x = __expf(-fmaxf(fmaf(-2.f, acc[mi][ni][0], xs0 + cs0), 0.f) * iv0);
            v0.y = __expf(-fmaxf(fmaf(-2.f, acc[mi][ni][1], xs0 + cs1), 0.f) * iv1);
            v1.x = __expf(-fmaxf(fmaf(-2.f, acc[mi][ni][2], xs1 + cs0), 0.f) * iv0);
            v1.y = __expf(-fmaxf(fmaf(-2.f, acc[mi][ni][3], xs1 + cs1), 0.f) * iv1);
            *(float2*)(out + (size_t)r0 * OUTN + c) = v0;
            *(float2*)(out + (size_t)r1 * OUTN + c) = v1;
        }
    }
}

// ---------------------------------------------------------------------------
extern "C" void kernel_launch(void* const* d_in, const int* in_sizes, int n_in,
                              void* d_out, int out_size) {
    const float* input   = (const float*)d_in[0];   // [B, IN]
    const float* centres = (const float*)d_in[1];   // [OUT, IN]
    const float* lsig    = (const float*)d_in[2];   // [OUT]
    float* out = (float*)d_out;

    const int OUTN = in_sizes[2];
    const int IN   = in_sizes[1] / OUTN;
    const int B    = in_sizes[0] / IN;

    __nv_bfloat16 *abf = nullptr, *cbf = nullptr;
    float *xsq = nullptr, *csq = nullptr, *inv = nullptr;
    cudaGetSymbolAddress((void**)&abf, g_Abf);
    cudaGetSymbolAddress((void**)&cbf, g_Cbf);
    cudaGetSymbolAddress((void**)&xsq, g_xsq);
    cudaGetSymbolAddress((void**)&csq, g_csq);
    cudaGetSymbolAddress((void**)&inv, g_inv);

    convert_norm_kernel<<<(B * 32 + 255) / 256, 256>>>(input, abf, xsq, B, IN);
    convert_norm_kernel<<<(OUTN * 32 + 255) / 256, 256>>>(centres, cbf, csq, OUTN, IN);
    sigma_kernel<<<(OUTN + 255) / 256, 256>>>(lsig, inv, OUTN);

    static bool attr_set = false;
    if (!attr_set) {
        cudaFuncSetAttribute(rbf_mma_kernel,
                             cudaFuncAttributeMaxDynamicSharedMemorySize, SMEM_TOTAL);
        attr_set = true;
    }
    dim3 grid(OUTN / 128, B / 128);
    rbf_mma_kernel<<<grid, 256, SMEM_TOTAL>>>(abf, cbf, out, xsq, csq, inv,
                                              IN, OUTN, IN / 64);
}

// round 4
// speedup vs baseline: 6.3481x; 1.0545x over previous
#include <cuda_runtime.h>
#include <cuda_bf16.h>
#include <cstdint>

// ===========================================================================
// RBF layer (sm_103, legacy tensor path: mma.sync bf16 + cp.async + ldmatrix)
//   out[b,o] = exp(-max(||x_b||^2 - 2 x_b.c_o + ||c_o||^2, 0) * exp(-2*ls_o))
// B=8192, IN=512, OUT=1024. GEMM in bf16 (numerically safe: d2 ~ 1024±64).
// tcgen05 unavailable: harness ptxas targets sm_103 (no 'a' features).
// R4: 3-stage cp.async pipeline (1 barrier/chunk), fused pre-pass.
// ===========================================================================

#define MAX_B   8192
#define MAX_OUT 1024
#define MAX_IN  512

__device__ __nv_bfloat16 g_Abf[MAX_B * MAX_IN];
__device__ __nv_bfloat16 g_Cbf[MAX_OUT * MAX_IN];
__device__ float g_xsq[MAX_B];
__device__ float g_csq[MAX_OUT];
__device__ float g_inv[MAX_OUT];

// ---------------------------------------------------------------------------
__device__ __forceinline__ uint32_t smem_to_u32(const void* smem_ptr) {
    uint32_t addr;
    asm("{ .reg .u64 tmp; cvta.to.shared.u64 tmp, %1; cvt.u32.u64 %0, tmp; }"
        : "=r"(addr) : "l"(smem_ptr));
    return addr;
}

#define SMEM_SWIZZLE_128B(byte_offset) \
    ((byte_offset) ^ (((byte_offset) >> 3) & 0x70))

#define CP_ASYNC16(dst_u32, src_ptr) \
    asm volatile("cp.async.cg.shared.global [%0], [%1], 16;" \
                 :: "r"(dst_u32), "l"(src_ptr) : "memory")
#define CP_COMMIT() asm volatile("cp.async.commit_group;" ::: "memory")
#define CP_WAIT1()  asm volatile("cp.async.wait_group 1;" ::: "memory")

#define LDSM4(r0, r1, r2, r3, addr) \
    asm volatile("ldmatrix.sync.aligned.m8n8.x4.shared.b16 {%0,%1,%2,%3}, [%4];" \
                 : "=r"(r0), "=r"(r1), "=r"(r2), "=r"(r3) : "r"(addr))

#define MMA16816(d, a, b) \
    asm volatile("mma.sync.aligned.m16n8k16.row.col.f32.bf16.bf16.f32 " \
                 "{%0,%1,%2,%3}, {%4,%5,%6,%7}, {%8,%9}, {%0,%1,%2,%3};" \
                 : "+f"((d)[0]), "+f"((d)[1]), "+f"((d)[2]), "+f"((d)[3]) \
                 : "r"((a)[0]), "r"((a)[1]), "r"((a)[2]), "r"((a)[3]), \
                   "r"((b)[0]), "r"((b)[1]))

// ---------------------------------------------------------------------------
// Fused pre-pass: one kernel, warp per row over [input rows | centre rows].
// fp32->bf16 convert + squared norm; centre rows also emit inv = exp(-2 ls).
// ---------------------------------------------------------------------------
__global__ void prep_kernel(const float* __restrict__ input,
                            const float* __restrict__ centres,
                            const float* __restrict__ lsig,
                            __nv_bfloat16* __restrict__ abf,
                            __nv_bfloat16* __restrict__ cbf,
                            float* __restrict__ xsq,
                            float* __restrict__ csq,
                            float* __restrict__ inv,
                            int B, int OUTN, int IN) {
    int warp = (blockIdx.x * blockDim.x + threadIdx.x) >> 5;
    int lane = threadIdx.x & 31;
    if (warp >= B + OUTN) return;

    const float* src;
    __nv_bfloat16* dst;
    float* nrm;
    if (warp < B) {
        src = input + (size_t)warp * IN;
        dst = g_Abf + (size_t)warp * IN;   (void)abf;
        nrm = xsq + warp;
    } else {
        int o = warp - B;
        src = centres + (size_t)o * IN;
        dst = g_Cbf + (size_t)o * IN;      (void)cbf;
        nrm = csq + o;
        if (lane == 1) inv[o] = __expf(-2.0f * lsig[o]);
    }

    const float4* p = (const float4*)src;
    uint4* q = (uint4*)dst;
    int n8 = IN >> 3;
    float s = 0.f;
    for (int i = lane; i < n8; i += 32) {
        float4 a = p[2 * i], b = p[2 * i + 1];
        s += a.x * a.x + a.y * a.y + a.z * a.z + a.w * a.w;
        s += b.x * b.x + b.y * b.y + b.z * b.z + b.w * b.w;
        union { __nv_bfloat162 h; uint32_t u; } c0, c1, c2, c3;
        c0.h = __floats2bfloat162_rn(a.x, a.y);
        c1.h = __floats2bfloat162_rn(a.z, a.w);
        c2.h = __floats2bfloat162_rn(b.x, b.y);
        c3.h = __floats2bfloat162_rn(b.z, b.w);
        uint4 v; v.x = c0.u; v.y = c1.u; v.z = c2.u; v.w = c3.u;
        q[i] = v;
    }
    #pragma unroll
    for (int o = 16; o; o >>= 1) s += __shfl_xor_sync(0xffffffffu, s, o);
    if (lane == 0) *nrm = s;
}

// ---------------------------------------------------------------------------
// GEMM + RBF epilogue.  CTA tile 128x128, BK=64 bf16, 8 warps (2Mx4N),
// warp tile 64x32, 3-stage cp.async pipeline, one barrier per K-chunk.
// ---------------------------------------------------------------------------
static constexpr int TILE_B  = 128 * 128;       // 16KB per operand tile/stage
static constexpr int STAGE_B = 2 * TILE_B;      // 32KB (A + B)
static constexpr int NSTAGE  = 3;
static constexpr int SMEM_TOTAL = NSTAGE * STAGE_B;  // 98304

__global__ __launch_bounds__(256, 2)
void rbf_mma_kernel(const __nv_bfloat16* __restrict__ gA,
                    const __nv_bfloat16* __restrict__ gC,
                    float* __restrict__ out,
                    const float* __restrict__ xsq,
                    const float* __restrict__ csq,
                    const float* __restrict__ inv,
                    int IN, int OUTN, int kchunks) {
    extern __shared__ char smem[];
    const uint32_t smem_u32 = smem_to_u32(smem);
    const int tid = threadIdx.x;
    const int lid = tid & 31;
    const int wid = tid >> 5;
    const int warp_m = wid >> 2;                 // 0..1 -> 64 rows
    const int warp_n = wid & 3;                  // 0..3 -> 32 cols
    const int brow = blockIdx.y * 128;
    const int bcol = blockIdx.x * 128;

    float acc[4][4][4];
    #pragma unroll
    for (int mi = 0; mi < 4; mi++)
        #pragma unroll
        for (int ni = 0; ni < 4; ni++)
            #pragma unroll
            for (int e = 0; e < 4; e++) acc[mi][ni][e] = 0.f;

    const int l_row = tid >> 3;                  // 0..31, +32*t
    const int l_q   = tid & 7;                   // 16B chunk within 128B row
    const size_t rowpitch = (size_t)IN * 2;

    const int a_row_l  = warp_m * 64 + (lid & 15);
    const int a_half   = (lid >> 4) & 1;
    const int b_row_l  = warp_n * 32 + ((lid >> 4) << 3) + (lid & 7);
    const int b_half   = (lid >> 3) & 1;

#define LOAD_STAGE(s, k0) do { \
    const char* srcA_ = (const char*)gA + 2 * ((size_t)brow * IN + (k0)); \
    const char* srcB_ = (const char*)gC + 2 * ((size_t)bcol * IN + (k0)); \
    uint32_t dstA_ = smem_u32 + (s) * STAGE_B; \
    uint32_t dstB_ = dstA_ + TILE_B; \
    _Pragma("unroll") \
    for (int t = 0; t < 4; t++) { \
        int row_ = l_row + 32 * t; \
        uint32_t sw_ = SMEM_SWIZZLE_128B((uint32_t)(row_ * 128 + l_q * 16)); \
        CP_ASYNC16(dstA_ + sw_, srcA_ + (size_t)row_ * rowpitch + l_q * 16); \
        CP_ASYNC16(dstB_ + sw_, srcB_ + (size_t)row_ * rowpitch + l_q * 16); \
    } \
} while (0)

    LOAD_STAGE(0, 0);
    CP_COMMIT();
    LOAD_STAGE(1, 64);
    CP_COMMIT();

    int s = 0;
    for (int i = 0; i < kchunks; i++) {
        CP_WAIT1();          // group i complete (group i+1 may be in flight)
        __syncthreads();     // all warps done reading slot being refilled below

        const uint32_t aBase = smem_u32 + s * STAGE_B;
        const uint32_t bBase = aBase + TILE_B;
        #pragma unroll
        for (int kk = 0; kk < 4; kk++) {
            uint32_t a[4][4], b[4][2];
            #pragma unroll
            for (int mi = 0; mi < 4; mi++) {
                int row = a_row_l + mi * 16;
                uint32_t addr = aBase + row * 128 +
                    (((uint32_t)(kk * 32 + a_half * 16)) ^ ((row & 7) << 4));
                LDSM4(a[mi][0], a[mi][1], a[mi][2], a[mi][3], addr);
            }
            #pragma unroll
            for (int nj = 0; nj < 2; nj++) {
                int row = b_row_l + nj * 16;
                uint32_t addr = bBase + row * 128 +
                    (((uint32_t)(kk * 32 + b_half * 16)) ^ ((row & 7) << 4));
                LDSM4(b[nj * 2][0], b[nj * 2][1], b[nj * 2 + 1][0], b[nj * 2 + 1][1], addr);
            }
            #pragma unroll
            for (int mi = 0; mi < 4; mi++)
                #pragma unroll
                for (int ni = 0; ni < 4; ni++)
                    MMA16816(acc[mi][ni], a[mi], b[ni]);
        }

        // refill slot (i+2)%3 == slot consumed at i-1 (safe past this iter's
        // barrier: every warp has finished compute of i-1 before reaching it)
        if (i + 2 < kchunks) {
            int s2 = s + 2; if (s2 >= NSTAGE) s2 -= NSTAGE;
            LOAD_STAGE(s2, (i + 2) * 64);
        }
        CP_COMMIT();
        if (++s == NSTAGE) s = 0;
    }

    // ---- fused RBF epilogue straight from accumulators --------------------
    const int er = lid >> 2;
    const int ec = (lid & 3) * 2;
    #pragma unroll
    for (int mi = 0; mi < 4; mi++) {
        const int r0 = brow + warp_m * 64 + mi * 16 + er;
        const int r1 = r0 + 8;
        const float xs0 = xsq[r0];
        const float xs1 = xsq[r1];
        #pragma unroll
        for (int ni = 0; ni < 4; ni++) {
            const int c = bcol + warp_n * 32 + ni * 8 + ec;
            const float cs0 = csq[c],  cs1 = csq[c + 1];
            const float iv0 = inv[c],  iv1 = inv[c + 1];
            float2 v0, v1;
            v0.x = __expf(-fmaxf(fmaf(-2.f, acc[mi][ni][0], xs0 + cs0), 0.f) * iv0);
            v0.y = __expf(-fmaxf(fmaf(-2.f, acc[mi][ni][1], xs0 + cs1), 0.f) * iv1);
            v1.x = __expf(-fmaxf(fmaf(-2.f, acc[mi][ni][2], xs1 + cs0), 0.f) * iv0);
            v1.y = __expf(-fmaxf(fmaf(-2.f, acc[mi][ni][3], xs1 + cs1), 0.f) * iv1);
            *(float2*)(out + (size_t)r0 * OUTN + c) = v0;
            *(float2*)(out + (size_t)r1 * OUTN + c) = v1;
        }
    }
}

// ---------------------------------------------------------------------------
extern "C" void kernel_launch(void* const* d_in, const int* in_sizes, int n_in,
                              void* d_out, int out_size) {
    const float* input   = (const float*)d_in[0];   // [B, IN]
    const float* centres = (const float*)d_in[1];   // [OUT, IN]
    const float* lsig    = (const float*)d_in[2];   // [OUT]
    float* out = (float*)d_out;

    const int OUTN = in_sizes[2];
    const int IN   = in_sizes[1] / OUTN;
    const int B    = in_sizes[0] / IN;

    __nv_bfloat16 *abf = nullptr, *cbf = nullptr;
    float *xsq = nullptr, *csq = nullptr, *inv = nullptr;
    cudaGetSymbolAddress((void**)&abf, g_Abf);
    cudaGetSymbolAddress((void**)&cbf, g_Cbf);
    cudaGetSymbolAddress((void**)&xsq, g_xsq);
    cudaGetSymbolAddress((void**)&csq, g_csq);
    cudaGetSymbolAddress((void**)&inv, g_inv);

    // fused pre-pass: (B + OUT) warps
    {
        int warps = B + OUTN;
        prep_kernel<<<(warps * 32 + 255) / 256, 256>>>(
            input, centres, lsig, abf, cbf, xsq, csq, inv, B, OUTN, IN);
    }

    static bool attr_set = false;
    if (!attr_set) {
        cudaFuncSetAttribute(rbf_mma_kernel,
                             cudaFuncAttributeMaxDynamicSharedMemorySize, SMEM_TOTAL);
        attr_set = true;
    }
    dim3 grid(OUTN / 128, B / 128);
    rbf_mma_kernel<<<grid, 256, SMEM_TOTAL>>>(abf, cbf, out, xsq, csq, inv,
                                              IN, OUTN, IN / 64);
}

// round 5
// speedup vs baseline: 6.7625x; 1.0653x over previous
#include <cuda_runtime.h>
#include <cuda_fp16.h>
#include <cstdint>

// ===========================================================================
// RBF layer (sm_103, legacy tensor path: mma.sync fp16 + cp.async + ldmatrix)
//   out[b,o] = exp(-max(||x_b||^2 - 2 x_b.c_o + ||c_o||^2, 0) * exp(-2*ls_o))
// B=8192, IN=512, OUT=1024.
// R5: fp16 inputs AND fp16 accumulators (2x HMMA rate, 32 acc regs),
//     explicit kk-level fragment double-buffering.
// Numerics: dot in [-200,200], fp16 accum error ~0.5 abs in d2; d2 ~ 1024+-64
// and exp(-d2) underflows with ~600 margin -> rel_err 0.
// tcgen05 unavailable: harness ptxas targets sm_103 (no 'a' features).
// ===========================================================================

#define MAX_B   8192
#define MAX_OUT 1024
#define MAX_IN  512

__device__ __half g_Ah[MAX_B * MAX_IN];
__device__ __half g_Ch[MAX_OUT * MAX_IN];
__device__ float g_xsq[MAX_B];
__device__ float g_csq[MAX_OUT];
__device__ float g_inv[MAX_OUT];

// ---------------------------------------------------------------------------
__device__ __forceinline__ uint32_t smem_to_u32(const void* smem_ptr) {
    uint32_t addr;
    asm("{ .reg .u64 tmp; cvta.to.shared.u64 tmp, %1; cvt.u32.u64 %0, tmp; }"
        : "=r"(addr) : "l"(smem_ptr));
    return addr;
}

#define SMEM_SWIZZLE_128B(byte_offset) \
    ((byte_offset) ^ (((byte_offset) >> 3) & 0x70))

#define CP_ASYNC16(dst_u32, src_ptr) \
    asm volatile("cp.async.cg.shared.global [%0], [%1], 16;" \
                 :: "r"(dst_u32), "l"(src_ptr) : "memory")
#define CP_COMMIT() asm volatile("cp.async.commit_group;" ::: "memory")
#define CP_WAIT1()  asm volatile("cp.async.wait_group 1;" ::: "memory")

#define LDSM4(r0, r1, r2, r3, addr) \
    asm volatile("ldmatrix.sync.aligned.m8n8.x4.shared.b16 {%0,%1,%2,%3}, [%4];" \
                 : "=r"(r0), "=r"(r1), "=r"(r2), "=r"(r3) : "r"(addr))

// fp16 in, fp16 accumulate: 2x tensor rate, 2 accumulator regs
#define MMA16816_F16(d, a, b) \
    asm volatile("mma.sync.aligned.m16n8k16.row.col.f16.f16.f16.f16 " \
                 "{%0,%1}, {%2,%3,%4,%5}, {%6,%7}, {%0,%1};" \
                 : "+r"((d)[0]), "+r"((d)[1]) \
                 : "r"((a)[0]), "r"((a)[1]), "r"((a)[2]), "r"((a)[3]), \
                   "r"((b)[0]), "r"((b)[1]))

// ---------------------------------------------------------------------------
// Fused pre-pass: warp per row over [input rows | centre rows].
// fp32->fp16 convert + squared norm (fp32); centre rows emit inv = exp(-2 ls).
// ---------------------------------------------------------------------------
__global__ void prep_kernel(const float* __restrict__ input,
                            const float* __restrict__ centres,
                            const float* __restrict__ lsig,
                            float* __restrict__ xsq,
                            float* __restrict__ csq,
                            float* __restrict__ inv,
                            int B, int OUTN, int IN) {
    int warp = (blockIdx.x * blockDim.x + threadIdx.x) >> 5;
    int lane = threadIdx.x & 31;
    if (warp >= B + OUTN) return;

    const float* src;
    __half* dst;
    float* nrm;
    if (warp < B) {
        src = input + (size_t)warp * IN;
        dst = g_Ah + (size_t)warp * IN;
        nrm = xsq + warp;
    } else {
        int o = warp - B;
        src = centres + (size_t)o * IN;
        dst = g_Ch + (size_t)o * IN;
        nrm = csq + o;
        if (lane == 1) inv[o] = __expf(-2.0f * lsig[o]);
    }

    const float4* p = (const float4*)src;
    uint4* q = (uint4*)dst;
    int n8 = IN >> 3;
    float s = 0.f;
    for (int i = lane; i < n8; i += 32) {
        float4 a = p[2 * i], b = p[2 * i + 1];
        s += a.x * a.x + a.y * a.y + a.z * a.z + a.w * a.w;
        s += b.x * b.x + b.y * b.y + b.z * b.z + b.w * b.w;
        union { __half2 h; uint32_t u; } c0, c1, c2, c3;
        c0.h = __floats2half2_rn(a.x, a.y);
        c1.h = __floats2half2_rn(a.z, a.w);
        c2.h = __floats2half2_rn(b.x, b.y);
        c3.h = __floats2half2_rn(b.z, b.w);
        uint4 v; v.x = c0.u; v.y = c1.u; v.z = c2.u; v.w = c3.u;
        q[i] = v;
    }
    #pragma unroll
    for (int o = 16; o; o >>= 1) s += __shfl_xor_sync(0xffffffffu, s, o);
    if (lane == 0) *nrm = s;
}

// ---------------------------------------------------------------------------
// GEMM + RBF epilogue.  CTA tile 128x128, BK=64 fp16, 8 warps (2Mx4N),
// warp tile 64x32, 3-stage cp.async pipeline, kk-level frag double-buffer.
// ---------------------------------------------------------------------------
static constexpr int TILE_B  = 128 * 128;       // 16KB per operand tile/stage
static constexpr int STAGE_B = 2 * TILE_B;      // 32KB (A + B)
static constexpr int NSTAGE  = 3;
static constexpr int SMEM_TOTAL = NSTAGE * STAGE_B;  // 98304

__global__ __launch_bounds__(256, 2)
void rbf_mma_kernel(const __half* __restrict__ gA,
                    const __half* __restrict__ gC,
                    float* __restrict__ out,
                    const float* __restrict__ xsq,
                    const float* __restrict__ csq,
                    const float* __restrict__ inv,
                    int IN, int OUTN, int kchunks) {
    extern __shared__ char smem[];
    const uint32_t smem_u32 = smem_to_u32(smem);
    const int tid = threadIdx.x;
    const int lid = tid & 31;
    const int wid = tid >> 5;
    const int warp_m = wid >> 2;                 // 0..1 -> 64 rows
    const int warp_n = wid & 3;                  // 0..3 -> 32 cols
    const int brow = blockIdx.y * 128;
    const int bcol = blockIdx.x * 128;

    uint32_t acc[4][4][2];                       // fp16x2 accumulators
    #pragma unroll
    for (int mi = 0; mi < 4; mi++)
        #pragma unroll
        for (int ni = 0; ni < 4; ni++) { acc[mi][ni][0] = 0u; acc[mi][ni][1] = 0u; }

    const int l_row = tid >> 3;
    const int l_q   = tid & 7;
    const size_t rowpitch = (size_t)IN * 2;

    const int a_row_l  = warp_m * 64 + (lid & 15);
    const int a_half   = (lid >> 4) & 1;
    const int b_row_l  = warp_n * 32 + ((lid >> 4) << 3) + (lid & 7);
    const int b_half   = (lid >> 3) & 1;

#define LOAD_STAGE(s, k0) do { \
    const char* srcA_ = (const char*)gA + 2 * ((size_t)brow * IN + (k0)); \
    const char* srcB_ = (const char*)gC + 2 * ((size_t)bcol * IN + (k0)); \
    uint32_t dstA_ = smem_u32 + (s) * STAGE_B; \
    uint32_t dstB_ = dstA_ + TILE_B; \
    _Pragma("unroll") \
    for (int t = 0; t < 4; t++) { \
        int row_ = l_row + 32 * t; \
        uint32_t sw_ = SMEM_SWIZZLE_128B((uint32_t)(row_ * 128 + l_q * 16)); \
        CP_ASYNC16(dstA_ + sw_, srcA_ + (size_t)row_ * rowpitch + l_q * 16); \
        CP_ASYNC16(dstB_ + sw_, srcB_ + (size_t)row_ * rowpitch + l_q * 16); \
    } \
} while (0)

// load A/B fragments for k-step kk into buffer bb
#define LOAD_FRAGS(bb, kk) do { \
    _Pragma("unroll") \
    for (int mi = 0; mi < 4; mi++) { \
        int row_ = a_row_l + mi * 16; \
        uint32_t addr_ = aBase + row_ * 128 + \
            (((uint32_t)((kk) * 32 + a_half * 16)) ^ ((row_ & 7) << 4)); \
        LDSM4(a[bb][mi][0], a[bb][mi][1], a[bb][mi][2], a[bb][mi][3], addr_); \
    } \
    _Pragma("unroll") \
    for (int nj = 0; nj < 2; nj++) { \
        int row_ = b_row_l + nj * 16; \
        uint32_t addr_ = bBase + row_ * 128 + \
            (((uint32_t)((kk) * 32 + b_half * 16)) ^ ((row_ & 7) << 4)); \
        LDSM4(b[bb][nj * 2][0], b[bb][nj * 2][1], \
              b[bb][nj * 2 + 1][0], b[bb][nj * 2 + 1][1], addr_); \
    } \
} while (0)

    LOAD_STAGE(0, 0);
    CP_COMMIT();
    LOAD_STAGE(1, 64);
    CP_COMMIT();

    int s = 0;
    for (int i = 0; i < kchunks; i++) {
        CP_WAIT1();
        __syncthreads();

        const uint32_t aBase = smem_u32 + s * STAGE_B;
        const uint32_t bBase = aBase + TILE_B;

        uint32_t a[2][4][4], b[2][4][2];
        LOAD_FRAGS(0, 0);
        #pragma unroll
        for (int kk = 0; kk < 4; kk++) {
            const int cur = kk & 1;
            if (kk < 3) LOAD_FRAGS(!cur, kk + 1);   // overlap lds with MMAs
            #pragma unroll
            for (int mi = 0; mi < 4; mi++)
                #pragma unroll
                for (int ni = 0; ni < 4; ni++)
                    MMA16816_F16(acc[mi][ni], a[cur][mi], b[cur][ni]);
        }

        if (i + 2 < kchunks) {
            int s2 = s + 2; if (s2 >= NSTAGE) s2 -= NSTAGE;
            LOAD_STAGE(s2, (i + 2) * 64);
        }
        CP_COMMIT();
        if (++s == NSTAGE) s = 0;
    }

    // ---- fused RBF epilogue straight from fp16 accumulators ---------------
    const int er = lid >> 2;
    const int ec = (lid & 3) * 2;
    #pragma unroll
    for (int mi = 0; mi < 4; mi++) {
        const int r0 = brow + warp_m * 64 + mi * 16 + er;
        const int r1 = r0 + 8;
        const float xs0 = xsq[r0];
        const float xs1 = xsq[r1];
        #pragma unroll
        for (int ni = 0; ni < 4; ni++) {
            const int c = bcol + warp_n * 32 + ni * 8 + ec;
            const float cs0 = csq[c],  cs1 = csq[c + 1];
            const float iv0 = inv[c],  iv1 = inv[c + 1];
            float2 d0 = __half22float2(*(const __half2*)&acc[mi][ni][0]);
            float2 d1 = __half22float2(*(const __half2*)&acc[mi][ni][1]);
            float2 v0, v1;
            v0.x = __expf(-fmaxf(fmaf(-2.f, d0.x, xs0 + cs0), 0.f) * iv0);
            v0.y = __expf(-fmaxf(fmaf(-2.f, d0.y, xs0 + cs1), 0.f) * iv1);
            v1.x = __expf(-fmaxf(fmaf(-2.f, d1.x, xs1 + cs0), 0.f) * iv0);
            v1.y = __expf(-fmaxf(fmaf(-2.f, d1.y, xs1 + cs1), 0.f) * iv1);
            *(float2*)(out + (size_t)r0 * OUTN + c) = v0;
            *(float2*)(out + (size_t)r1 * OUTN + c) = v1;
        }
    }
}

// ---------------------------------------------------------------------------
extern "C" void kernel_launch(void* const* d_in, const int* in_sizes, int n_in,
                              void* d_out, int out_size) {
    const float* input   = (const float*)d_in[0];   // [B, IN]
    const float* centres = (const float*)d_in[1];   // [OUT, IN]
    const float* lsig    = (const float*)d_in[2];   // [OUT]
    float* out = (float*)d_out;

    const int OUTN = in_sizes[2];
    const int IN   = in_sizes[1] / OUTN;
    const int B    = in_sizes[0] / IN;

    __half *ah = nullptr, *ch = nullptr;
    float *xsq = nullptr, *csq = nullptr, *inv = nullptr;
    cudaGetSymbolAddress((void**)&ah, g_Ah);
    cudaGetSymbolAddress((void**)&ch, g_Ch);
    cudaGetSymbolAddress((void**)&xsq, g_xsq);
    cudaGetSymbolAddress((void**)&csq, g_csq);
    cudaGetSymbolAddress((void**)&inv, g_inv);

    {
        int warps = B + OUTN;
        prep_kernel<<<(warps * 32 + 255) / 256, 256>>>(
            input, centres, lsig, xsq, csq, inv, B, OUTN, IN);
    }

    static bool attr_set = false;
    if (!attr_set) {
        cudaFuncSetAttribute(rbf_mma_kernel,
                             cudaFuncAttributeMaxDynamicSharedMemorySize, SMEM_TOTAL);
        attr_set = true;
    }
    dim3 grid(OUTN / 128, B / 128);
    rbf_mma_kernel<<<grid, 256, SMEM_TOTAL>>>(ah, ch, out, xsq, csq, inv,
                                              IN, OUTN, IN / 64);
}